// round 6
// baseline (speedup 1.0000x reference)
#include <cuda_runtime.h>
#include <cstdint>

#define NN   50000
#define EE   1600000
#define FIN  512
#define F1   64        // H1*C1
#define NH1  8
#define C2   40
#define NBLK 196       // ceil(NN/256)
#define FULLM 0xffffffffu

// ------------------------- scratch (static device memory; no allocs allowed)
__device__ float g_h1[NN * F1];
__device__ float g_as1[NN * NH1];
__device__ float g_ad1[NN * NH1];
__device__ float g_h2[NN * C2];
__device__ float g_as2[NN];
__device__ float g_ad2[NN];
__device__ int   g_deg[NN];
__device__ int   g_rowloc[NN];
__device__ int   g_bsum[256];
__device__ int   g_boff[256];
__device__ int   g_rowptr[NN + 1];
__device__ int   g_cursor[NN];
__device__ int   g_col[EE];

__device__ __forceinline__ float leaky(float v) { return v > 0.f ? v : 0.2f * v; }

__device__ __forceinline__ uint32_t f2tf(float f) {
    uint32_t u;
    asm("cvt.rna.tf32.f32 %0, %1;" : "=r"(u) : "f"(f));
    return u;
}

__device__ __forceinline__ void mma_tf32(float* d, const uint32_t* a, const uint32_t* b) {
    asm volatile(
        "mma.sync.aligned.m16n8k8.row.col.f32.tf32.tf32.f32 "
        "{%0,%1,%2,%3}, {%4,%5,%6,%7}, {%8,%9}, {%0,%1,%2,%3};"
        : "+f"(d[0]), "+f"(d[1]), "+f"(d[2]), "+f"(d[3])
        : "r"(a[0]), "r"(a[1]), "r"(a[2]), "r"(a[3]), "r"(b[0]), "r"(b[1]));
}

// ------------------------- GEMM1 (tf32 tensor cores) + fused attention coeffs
__global__ __launch_bounds__(256) void k_gemm1(const float* __restrict__ x,
                                               const float* __restrict__ W1,
                                               const float* __restrict__ attS,
                                               const float* __restrict__ attD) {
    __shared__ float sA[128][36];
    __shared__ float sB[32][72];
    __shared__ float sAs[64], sAd[64];

    const int t    = threadIdx.x;
    const int wid  = t >> 5;
    const int lane = t & 31;
    const int m0   = blockIdx.x * 128;
    const int warp_m = (wid >> 1) * 32;
    const int warp_n = (wid & 1) * 32;
    if (t < 64) { sAs[t] = attS[t]; sAd[t] = attD[t]; }

    float acc[2][4][4];
#pragma unroll
    for (int mi = 0; mi < 2; mi++)
#pragma unroll
        for (int ni = 0; ni < 4; ni++)
#pragma unroll
            for (int e = 0; e < 4; e++) acc[mi][ni][e] = 0.f;

    const int r = lane >> 2;
    const int c = lane & 3;
    const int arow = t >> 3;
    const int acol = (t & 7) * 4;

    for (int kc = 0; kc < FIN; kc += 32) {
#pragma unroll
        for (int i = 0; i < 4; i++) {
            int row = i * 32 + arow;
            int gm  = m0 + row;
            float4 v = (gm < NN) ? *(const float4*)&x[(long)gm * FIN + kc + acol]
                                 : make_float4(0.f, 0.f, 0.f, 0.f);
            float4 tv;
            tv.x = __uint_as_float(f2tf(v.x));
            tv.y = __uint_as_float(f2tf(v.y));
            tv.z = __uint_as_float(f2tf(v.z));
            tv.w = __uint_as_float(f2tf(v.w));
            *(float4*)&sA[row][acol] = tv;
        }
#pragma unroll
        for (int i = 0; i < 2; i++) {
            int f   = t + i * 256;
            int row = f >> 4;
            int c4  = (f & 15) * 4;
            float4 v = *(const float4*)&W1[(kc + row) * F1 + c4];
            float4 tv;
            tv.x = __uint_as_float(f2tf(v.x));
            tv.y = __uint_as_float(f2tf(v.y));
            tv.z = __uint_as_float(f2tf(v.z));
            tv.w = __uint_as_float(f2tf(v.w));
            *(float4*)&sB[row][c4] = tv;
        }
        __syncthreads();

#pragma unroll
        for (int ks = 0; ks < 4; ks++) {
            const int k0 = ks * 8;
            uint32_t afrag[2][4];
#pragma unroll
            for (int mi = 0; mi < 2; mi++) {
                int mm = warp_m + mi * 16;
                afrag[mi][0] = __float_as_uint(sA[mm + r][k0 + c]);
                afrag[mi][1] = __float_as_uint(sA[mm + r + 8][k0 + c]);
                afrag[mi][2] = __float_as_uint(sA[mm + r][k0 + c + 4]);
                afrag[mi][3] = __float_as_uint(sA[mm + r + 8][k0 + c + 4]);
            }
            uint32_t bfrag[4][2];
#pragma unroll
            for (int ni = 0; ni < 4; ni++) {
                int nn = warp_n + ni * 8;
                bfrag[ni][0] = __float_as_uint(sB[k0 + c][nn + r]);
                bfrag[ni][1] = __float_as_uint(sB[k0 + c + 4][nn + r]);
            }
#pragma unroll
            for (int mi = 0; mi < 2; mi++)
#pragma unroll
                for (int ni = 0; ni < 4; ni++)
                    mma_tf32(acc[mi][ni], afrag[mi], bfrag[ni]);
        }
        __syncthreads();
    }

#pragma unroll
    for (int mi = 0; mi < 2; mi++) {
        int row_g = m0 + warp_m + mi * 16 + r;
        int row_h = row_g + 8;
#pragma unroll
        for (int ni = 0; ni < 4; ni++) {
            int nn = warp_n + ni * 8;
            int col = nn + c * 2;
            if (row_g < NN)
                *(float2*)&g_h1[row_g * F1 + col] = make_float2(acc[mi][ni][0], acc[mi][ni][1]);
            if (row_h < NN)
                *(float2*)&g_h1[row_h * F1 + col] = make_float2(acc[mi][ni][2], acc[mi][ni][3]);
            float as0 = sAs[col], as1v = sAs[col + 1];
            float ad0 = sAd[col], ad1v = sAd[col + 1];
            float psg = acc[mi][ni][0] * as0 + acc[mi][ni][1] * as1v;
            float pdg = acc[mi][ni][0] * ad0 + acc[mi][ni][1] * ad1v;
            float psh = acc[mi][ni][2] * as0 + acc[mi][ni][3] * as1v;
            float pdh = acc[mi][ni][2] * ad0 + acc[mi][ni][3] * ad1v;
#pragma unroll
            for (int off = 1; off <= 2; off <<= 1) {
                psg += __shfl_xor_sync(FULLM, psg, off);
                pdg += __shfl_xor_sync(FULLM, pdg, off);
                psh += __shfl_xor_sync(FULLM, psh, off);
                pdh += __shfl_xor_sync(FULLM, pdh, off);
            }
            int h = nn >> 3;
            if (c == 0) {
                if (row_g < NN) { g_as1[row_g * NH1 + h] = psg; g_ad1[row_g * NH1 + h] = pdg; }
                if (row_h < NN) { g_as1[row_h * NH1 + h] = psh; g_ad1[row_h * NH1 + h] = pdh; }
            }
        }
    }
}

// ------------------------- CSR build
__global__ void k_zero() {
    int i = blockIdx.x * blockDim.x + threadIdx.x;
    if (i < NN) g_deg[i] = 0;
}
__global__ void k_hist(const int* __restrict__ dst) {
    int e4 = blockIdx.x * blockDim.x + threadIdx.x;
    if (e4 < EE / 4) {
        int4 d = ((const int4*)dst)[e4];
        atomicAdd(&g_deg[d.x], 1);
        atomicAdd(&g_deg[d.y], 1);
        atomicAdd(&g_deg[d.z], 1);
        atomicAdd(&g_deg[d.w], 1);
    }
}
__global__ __launch_bounds__(256) void k_part() {
    __shared__ int sm[256];
    int t = threadIdx.x, i = blockIdx.x * 256 + t;
    int d = (i < NN) ? g_deg[i] : 0;
    sm[t] = d;
    __syncthreads();
#pragma unroll
    for (int off = 1; off < 256; off <<= 1) {
        int v = (t >= off) ? sm[t - off] : 0;
        __syncthreads();
        sm[t] += v;
        __syncthreads();
    }
    if (i < NN) g_rowloc[i] = sm[t] - d;
    if (t == 255) g_bsum[blockIdx.x] = sm[255];
}
__global__ __launch_bounds__(256) void k_bscan() {
    __shared__ int sm[256];
    int t = threadIdx.x;
    int d = (t < NBLK) ? g_bsum[t] : 0;
    sm[t] = d;
    __syncthreads();
#pragma unroll
    for (int off = 1; off < 256; off <<= 1) {
        int v = (t >= off) ? sm[t - off] : 0;
        __syncthreads();
        sm[t] += v;
        __syncthreads();
    }
    if (t < NBLK) g_boff[t] = sm[t] - d;
    if (t == NBLK - 1) g_rowptr[NN] = sm[t];
}
__global__ void k_fix() {
    int i = blockIdx.x * blockDim.x + threadIdx.x;
    if (i < NN) {
        int rp = g_rowloc[i] + g_boff[blockIdx.x];
        g_rowptr[i] = rp;
        g_cursor[i] = rp;
    }
}
__global__ void k_scatter(const int* __restrict__ src, const int* __restrict__ dst) {
    int e4 = blockIdx.x * blockDim.x + threadIdx.x;
    if (e4 < EE / 4) {
        int4 s = ((const int4*)src)[e4];
        int4 d = ((const int4*)dst)[e4];
        g_col[atomicAdd(&g_cursor[d.x], 1)] = s.x;
        g_col[atomicAdd(&g_cursor[d.y], 1)] = s.y;
        g_col[atomicAdd(&g_cursor[d.z], 1)] = s.z;
        g_col[atomicAdd(&g_cursor[d.w], 1)] = s.w;
    }
}

// ------------------------- layer-1 aggregation + fused layer-2 linear/att
// TWO warps per node: interleaved 32-edge chunks; partials merged via smem.
// Block = 256 threads = 8 warps = 4 nodes. NN % 4 == 0.
__global__ __launch_bounds__(256) void k_agg1(const float* __restrict__ b1,
                                              const float* __restrict__ W2,
                                              const float* __restrict__ att_s,
                                              const float* __restrict__ att_d) {
    __shared__ float swt[8][8][36];   // [warp][head][edge slot]
    __shared__ int   ssrc[8][32];
    __shared__ float racc[8][64];     // per-warp channel partials
    __shared__ float rsum[8][8];      // per-warp head denominators
    __shared__ float sW2[F1 * C2];
    __shared__ float sAs2[C2], sAd2[C2];

    for (int idx = threadIdx.x; idx < F1 * C2; idx += 256) sW2[idx] = W2[idx];
    if (threadIdx.x < C2) {
        sAs2[threadIdx.x] = att_s[threadIdx.x];
        sAd2[threadIdx.x] = att_d[threadIdx.x];
    }
    __syncthreads();

    const int w    = threadIdx.x >> 5;
    const int lane = threadIdx.x & 31;
    const int half = w & 1;                  // which of the node's two warps
    const int node = blockIdx.x * 4 + (w >> 1);
    const int beg   = g_rowptr[node];
    const int deg   = g_rowptr[node + 1] - beg;
    const int total = deg + 1;               // + self loop (handled by half 0)

    float4 ad0 = *(const float4*)&g_ad1[node * 8];
    float4 ad1 = *(const float4*)&g_ad1[node * 8 + 4];
    float adr[8] = { ad0.x, ad0.y, ad0.z, ad0.w, ad1.x, ad1.y, ad1.z, ad1.w };

    const int hl = lane >> 2;
    const int c0 = lane * 2;
    float acc0 = 0.f, acc1 = 0.f;
    float ssum[8];
#pragma unroll
    for (int h = 0; h < 8; h++) ssum[h] = 0.f;

    for (int k0 = half * 32; k0 < total; k0 += 64) {
        int kk  = k0 + lane;
        int lim = min(32, total - k0);
        __syncwarp();
        if (kk < total) {
            int srcn = (kk < deg) ? g_col[beg + kk] : node;
            float4 s0 = *(const float4*)&g_as1[srcn * 8];
            float4 s1 = *(const float4*)&g_as1[srcn * 8 + 4];
            float lg[8] = { s0.x + adr[0], s0.y + adr[1], s0.z + adr[2], s0.w + adr[3],
                            s1.x + adr[4], s1.y + adr[5], s1.z + adr[6], s1.w + adr[7] };
#pragma unroll
            for (int h = 0; h < 8; h++) {
                float wt = __expf(leaky(lg[h]));
                ssum[h] += wt;
                swt[w][h][lane] = wt;
            }
            ssrc[w][lane] = srcn;
        }
        __syncwarp();
        for (int j = 0; j < lim; j++) {
            int srcn = ssrc[w][j];
            float wt = swt[w][hl][j];
            float2 hv = *(const float2*)&g_h1[srcn * F1 + c0];
            acc0 += wt * hv.x;
            acc1 += wt * hv.y;
        }
    }
    // warp-internal denominator reduce
#pragma unroll
    for (int h = 0; h < 8; h++) {
#pragma unroll
        for (int off = 16; off > 0; off >>= 1)
            ssum[h] += __shfl_xor_sync(FULLM, ssum[h], off);
    }
    // publish partials
    racc[w][c0]     = acc0;
    racc[w][c0 + 1] = acc1;
    if (lane == 0) {
#pragma unroll
        for (int h = 0; h < 8; h++) rsum[w][h] = ssum[h];
    }
    __syncthreads();
    if (half) return;

    // merge partner warp (w+1)
    acc0 += racc[w + 1][c0];
    acc1 += racc[w + 1][c0 + 1];
    float myS = rsum[w][hl] + rsum[w + 1][hl];
    float inv = __fdividef(1.0f, myS);

    // x2 row in registers (relu + bias)
    float v0 = fmaxf(acc0 * inv + b1[c0], 0.f);
    float v1 = fmaxf(acc1 * inv + b1[c0 + 1], 0.f);

    // fused layer-2 linear: h2 = x2 @ W2  (+ attention coefficients)
    const int cA = lane;
    const int cB = lane + 32;
    const bool has1 = (lane < 8);
    float a0 = 0.f, a1 = 0.f;
#pragma unroll
    for (int kk = 0; kk < 32; kk++) {
        float x0 = __shfl_sync(FULLM, v0, kk);
        float x1 = __shfl_sync(FULLM, v1, kk);
        a0 += x0 * sW2[(2 * kk) * C2 + cA] + x1 * sW2[(2 * kk + 1) * C2 + cA];
        if (has1)
            a1 += x0 * sW2[(2 * kk) * C2 + cB] + x1 * sW2[(2 * kk + 1) * C2 + cB];
    }
    g_h2[node * C2 + cA] = a0;
    if (has1) g_h2[node * C2 + cB] = a1;

    float ps = a0 * sAs2[cA] + (has1 ? a1 * sAs2[cB] : 0.f);
    float pd = a0 * sAd2[cA] + (has1 ? a1 * sAd2[cB] : 0.f);
#pragma unroll
    for (int off = 16; off > 0; off >>= 1) {
        ps += __shfl_xor_sync(FULLM, ps, off);
        pd += __shfl_xor_sync(FULLM, pd, off);
    }
    if (lane == 0) { g_as2[node] = ps; g_ad2[node] = pd; }
}

// ------------------------- layer-2 aggregation + bias + log_softmax
// TWO warps per node, same chunk interleave.
__global__ __launch_bounds__(256) void k_agg2(const float* __restrict__ b2,
                                              float* __restrict__ out) {
    __shared__ float swt[8][32];
    __shared__ int   ssrc[8][32];
    __shared__ float racc[8][64];
    __shared__ float rsum[8];
    const int w    = threadIdx.x >> 5;
    const int lane = threadIdx.x & 31;
    const int half = w & 1;
    const int node = blockIdx.x * 4 + (w >> 1);
    const int beg   = g_rowptr[node];
    const int deg   = g_rowptr[node + 1] - beg;
    const int total = deg + 1;
    const float adn = g_ad2[node];

    const int c0 = lane;
    const int c1 = lane + 32;
    const bool has1 = (c1 < C2);
    float acc0 = 0.f, acc1 = 0.f, ssum = 0.f;
    for (int k0 = half * 32; k0 < total; k0 += 64) {
        int kk  = k0 + lane;
        int lim = min(32, total - k0);
        __syncwarp();
        if (kk < total) {
            int srcn = (kk < deg) ? g_col[beg + kk] : node;
            float wt = __expf(leaky(g_as2[srcn] + adn));
            ssum += wt;
            swt[w][lane]  = wt;
            ssrc[w][lane] = srcn;
        }
        __syncwarp();
        for (int j = 0; j < lim; j++) {
            int srcn = ssrc[w][j];
            float wt = swt[w][j];
            acc0 += wt * g_h2[srcn * C2 + c0];
            if (has1) acc1 += wt * g_h2[srcn * C2 + c1];
        }
    }
#pragma unroll
    for (int off = 16; off > 0; off >>= 1)
        ssum += __shfl_xor_sync(FULLM, ssum, off);

    racc[w][lane]      = acc0;
    racc[w][lane + 32] = acc1;
    if (lane == 0) rsum[w] = ssum;
    __syncthreads();
    if (half) return;

    acc0 += racc[w + 1][lane];
    acc1 += racc[w + 1][lane + 32];
    ssum = rsum[w] + rsum[w + 1];
    float inv = __fdividef(1.0f, ssum);

    float o0 = acc0 * inv + b2[c0];
    float o1 = has1 ? (acc1 * inv + b2[c1]) : -1e30f;

    float mx = fmaxf(o0, o1);
#pragma unroll
    for (int off = 16; off > 0; off >>= 1)
        mx = fmaxf(mx, __shfl_xor_sync(FULLM, mx, off));
    float se = __expf(o0 - mx) + (has1 ? __expf(o1 - mx) : 0.f);
#pragma unroll
    for (int off = 16; off > 0; off >>= 1)
        se += __shfl_xor_sync(FULLM, se, off);
    float lse = mx + __logf(se);

    out[node * C2 + c0] = o0 - lse;
    if (has1) out[node * C2 + c1] = o1 - lse;
}

// ------------------------- launch
extern "C" void kernel_launch(void* const* d_in, const int* in_sizes, int n_in,
                              void* d_out, int out_size) {
    const float* x        = (const float*)d_in[0];
    const int*   ei       = (const int*)d_in[1];
    const float* W1       = (const float*)d_in[2];
    const float* att_src1 = (const float*)d_in[3];
    const float* att_dst1 = (const float*)d_in[4];
    const float* b1       = (const float*)d_in[5];
    const float* W2       = (const float*)d_in[6];
    const float* att_src2 = (const float*)d_in[7];
    const float* att_dst2 = (const float*)d_in[8];
    const float* b2       = (const float*)d_in[9];
    float* out = (float*)d_out;

    const int* src = ei;
    const int* dst = ei + EE;

    // CSR build
    k_zero<<<(NN + 255) / 256, 256>>>();
    k_hist<<<(EE / 4 + 255) / 256, 256>>>(dst);
    k_part<<<NBLK, 256>>>();
    k_bscan<<<1, 256>>>();
    k_fix<<<NBLK, 256>>>();
    k_scatter<<<(EE / 4 + 255) / 256, 256>>>(src, dst);

    // layer 1 (tf32 tensor-core GEMM + fused att coeffs)
    k_gemm1<<<(NN + 127) / 128, 256>>>(x, W1, att_src1, att_dst1);

    // layer-1 aggregation (2 warps/node) fused with layer-2 linear + att coeffs
    k_agg1<<<NN / 4, 256>>>(b1, W2, att_src2, att_dst2);

    // layer-2 aggregation (2 warps/node) + log_softmax
    k_agg2<<<NN / 4, 256>>>(b2, out);
}

// round 7
// speedup vs baseline: 1.2406x; 1.2406x over previous
#include <cuda_runtime.h>
#include <cstdint>

#define NN   50000
#define EE   1600000
#define FIN  512
#define F1   64        // H1*C1
#define NH1  8
#define C2   40
#define NBLK 196       // ceil(NN/256)
#define FULLM 0xffffffffu

// ------------------------- scratch (static device memory; no allocs allowed)
__device__ float g_h1[NN * F1];
__device__ float g_as1[NN * NH1];
__device__ float g_ad1[NN * NH1];
__device__ float g_h2[NN * C2];
__device__ float g_as2[NN];
__device__ float g_ad2[NN];
__device__ int   g_deg[NN];
__device__ int   g_rowloc[NN];
__device__ int   g_bsum[256];
__device__ int   g_boff[256];
__device__ int   g_rowptr[NN + 1];
__device__ int   g_cursor[NN];
__device__ int   g_col[EE];

__device__ __forceinline__ float leaky(float v) { return v > 0.f ? v : 0.2f * v; }

__device__ __forceinline__ uint32_t f2tf(float f) {
    uint32_t u;
    asm("cvt.rna.tf32.f32 %0, %1;" : "=r"(u) : "f"(f));
    return u;
}

__device__ __forceinline__ void mma_tf32(float* d, const uint32_t* a, const uint32_t* b) {
    asm volatile(
        "mma.sync.aligned.m16n8k8.row.col.f32.tf32.tf32.f32 "
        "{%0,%1,%2,%3}, {%4,%5,%6,%7}, {%8,%9}, {%0,%1,%2,%3};"
        : "+f"(d[0]), "+f"(d[1]), "+f"(d[2]), "+f"(d[3])
        : "r"(a[0]), "r"(a[1]), "r"(a[2]), "r"(a[3]), "r"(b[0]), "r"(b[1]));
}

// ------------------------- GEMM1 (tf32 tensor cores) + fused attention coeffs
__global__ __launch_bounds__(256) void k_gemm1(const float* __restrict__ x,
                                               const float* __restrict__ W1,
                                               const float* __restrict__ attS,
                                               const float* __restrict__ attD) {
    __shared__ float sA[128][36];
    __shared__ float sB[32][72];
    __shared__ float sAs[64], sAd[64];

    const int t    = threadIdx.x;
    const int wid  = t >> 5;
    const int lane = t & 31;
    const int m0   = blockIdx.x * 128;
    const int warp_m = (wid >> 1) * 32;
    const int warp_n = (wid & 1) * 32;
    if (t < 64) { sAs[t] = attS[t]; sAd[t] = attD[t]; }

    float acc[2][4][4];
#pragma unroll
    for (int mi = 0; mi < 2; mi++)
#pragma unroll
        for (int ni = 0; ni < 4; ni++)
#pragma unroll
            for (int e = 0; e < 4; e++) acc[mi][ni][e] = 0.f;

    const int r = lane >> 2;
    const int c = lane & 3;
    const int arow = t >> 3;
    const int acol = (t & 7) * 4;

    for (int kc = 0; kc < FIN; kc += 32) {
#pragma unroll
        for (int i = 0; i < 4; i++) {
            int row = i * 32 + arow;
            int gm  = m0 + row;
            float4 v = (gm < NN) ? *(const float4*)&x[(long)gm * FIN + kc + acol]
                                 : make_float4(0.f, 0.f, 0.f, 0.f);
            float4 tv;
            tv.x = __uint_as_float(f2tf(v.x));
            tv.y = __uint_as_float(f2tf(v.y));
            tv.z = __uint_as_float(f2tf(v.z));
            tv.w = __uint_as_float(f2tf(v.w));
            *(float4*)&sA[row][acol] = tv;
        }
#pragma unroll
        for (int i = 0; i < 2; i++) {
            int f   = t + i * 256;
            int row = f >> 4;
            int c4  = (f & 15) * 4;
            float4 v = *(const float4*)&W1[(kc + row) * F1 + c4];
            float4 tv;
            tv.x = __uint_as_float(f2tf(v.x));
            tv.y = __uint_as_float(f2tf(v.y));
            tv.z = __uint_as_float(f2tf(v.z));
            tv.w = __uint_as_float(f2tf(v.w));
            *(float4*)&sB[row][c4] = tv;
        }
        __syncthreads();

#pragma unroll
        for (int ks = 0; ks < 4; ks++) {
            const int k0 = ks * 8;
            uint32_t afrag[2][4];
#pragma unroll
            for (int mi = 0; mi < 2; mi++) {
                int mm = warp_m + mi * 16;
                afrag[mi][0] = __float_as_uint(sA[mm + r][k0 + c]);
                afrag[mi][1] = __float_as_uint(sA[mm + r + 8][k0 + c]);
                afrag[mi][2] = __float_as_uint(sA[mm + r][k0 + c + 4]);
                afrag[mi][3] = __float_as_uint(sA[mm + r + 8][k0 + c + 4]);
            }
            uint32_t bfrag[4][2];
#pragma unroll
            for (int ni = 0; ni < 4; ni++) {
                int nn = warp_n + ni * 8;
                bfrag[ni][0] = __float_as_uint(sB[k0 + c][nn + r]);
                bfrag[ni][1] = __float_as_uint(sB[k0 + c + 4][nn + r]);
            }
#pragma unroll
            for (int mi = 0; mi < 2; mi++)
#pragma unroll
                for (int ni = 0; ni < 4; ni++)
                    mma_tf32(acc[mi][ni], afrag[mi], bfrag[ni]);
        }
        __syncthreads();
    }

#pragma unroll
    for (int mi = 0; mi < 2; mi++) {
        int row_g = m0 + warp_m + mi * 16 + r;
        int row_h = row_g + 8;
#pragma unroll
        for (int ni = 0; ni < 4; ni++) {
            int nn = warp_n + ni * 8;
            int col = nn + c * 2;
            if (row_g < NN)
                *(float2*)&g_h1[row_g * F1 + col] = make_float2(acc[mi][ni][0], acc[mi][ni][1]);
            if (row_h < NN)
                *(float2*)&g_h1[row_h * F1 + col] = make_float2(acc[mi][ni][2], acc[mi][ni][3]);
            float as0 = sAs[col], as1v = sAs[col + 1];
            float ad0 = sAd[col], ad1v = sAd[col + 1];
            float psg = acc[mi][ni][0] * as0 + acc[mi][ni][1] * as1v;
            float pdg = acc[mi][ni][0] * ad0 + acc[mi][ni][1] * ad1v;
            float psh = acc[mi][ni][2] * as0 + acc[mi][ni][3] * as1v;
            float pdh = acc[mi][ni][2] * ad0 + acc[mi][ni][3] * ad1v;
#pragma unroll
            for (int off = 1; off <= 2; off <<= 1) {
                psg += __shfl_xor_sync(FULLM, psg, off);
                pdg += __shfl_xor_sync(FULLM, pdg, off);
                psh += __shfl_xor_sync(FULLM, psh, off);
                pdh += __shfl_xor_sync(FULLM, pdh, off);
            }
            int h = nn >> 3;
            if (c == 0) {
                if (row_g < NN) { g_as1[row_g * NH1 + h] = psg; g_ad1[row_g * NH1 + h] = pdg; }
                if (row_h < NN) { g_as1[row_h * NH1 + h] = psh; g_ad1[row_h * NH1 + h] = pdh; }
            }
        }
    }
}

// ------------------------- CSR build
__global__ void k_zero() {
    int i = blockIdx.x * blockDim.x + threadIdx.x;
    if (i < NN) g_deg[i] = 0;
}
__global__ void k_hist(const int* __restrict__ dst) {
    int e = blockIdx.x * blockDim.x + threadIdx.x;
    if (e < EE) atomicAdd(&g_deg[dst[e]], 1);
}
__global__ __launch_bounds__(256) void k_part() {
    __shared__ int sm[256];
    int t = threadIdx.x, i = blockIdx.x * 256 + t;
    int d = (i < NN) ? g_deg[i] : 0;
    sm[t] = d;
    __syncthreads();
#pragma unroll
    for (int off = 1; off < 256; off <<= 1) {
        int v = (t >= off) ? sm[t - off] : 0;
        __syncthreads();
        sm[t] += v;
        __syncthreads();
    }
    if (i < NN) g_rowloc[i] = sm[t] - d;
    if (t == 255) g_bsum[blockIdx.x] = sm[255];
}
__global__ __launch_bounds__(256) void k_bscan() {
    __shared__ int sm[256];
    int t = threadIdx.x;
    int d = (t < NBLK) ? g_bsum[t] : 0;
    sm[t] = d;
    __syncthreads();
#pragma unroll
    for (int off = 1; off < 256; off <<= 1) {
        int v = (t >= off) ? sm[t - off] : 0;
        __syncthreads();
        sm[t] += v;
        __syncthreads();
    }
    if (t < NBLK) g_boff[t] = sm[t] - d;
    if (t == NBLK - 1) g_rowptr[NN] = sm[t];
}
__global__ void k_fix() {
    int i = blockIdx.x * blockDim.x + threadIdx.x;
    if (i < NN) {
        int rp = g_rowloc[i] + g_boff[blockIdx.x];
        g_rowptr[i] = rp;
        g_cursor[i] = rp;
    }
}
__global__ void k_scatter(const int* __restrict__ src, const int* __restrict__ dst) {
    int e = blockIdx.x * blockDim.x + threadIdx.x;
    if (e < EE) {
        int d = dst[e];
        int p = atomicAdd(&g_cursor[d], 1);
        g_col[p] = src[e];
    }
}

// ------------------------- layer-1 aggregation + fused layer-2 linear/att
// one warp per dst node; no max pass (logits are tiny; softmax shift-invariant)
__global__ __launch_bounds__(256) void k_agg1(const float* __restrict__ b1,
                                              const float* __restrict__ W2,
                                              const float* __restrict__ att_s,
                                              const float* __restrict__ att_d) {
    __shared__ float swt[8][8][36];
    __shared__ int   ssrc[8][32];
    __shared__ float sW2[F1 * C2];
    __shared__ float sAs2[C2], sAd2[C2];

    for (int idx = threadIdx.x; idx < F1 * C2; idx += 256) sW2[idx] = W2[idx];
    if (threadIdx.x < C2) {
        sAs2[threadIdx.x] = att_s[threadIdx.x];
        sAd2[threadIdx.x] = att_d[threadIdx.x];
    }
    __syncthreads();

    const int w    = threadIdx.x >> 5;
    const int lane = threadIdx.x & 31;
    const int node = blockIdx.x * 8 + w;
    if (node >= NN) return;
    const int beg   = g_rowptr[node];
    const int deg   = g_rowptr[node + 1] - beg;
    const int total = deg + 1;

    float4 ad0 = *(const float4*)&g_ad1[node * 8];
    float4 ad1 = *(const float4*)&g_ad1[node * 8 + 4];
    float adr[8] = { ad0.x, ad0.y, ad0.z, ad0.w, ad1.x, ad1.y, ad1.z, ad1.w };

    const int hl = lane >> 2;
    const int c0 = lane * 2;
    float acc0 = 0.f, acc1 = 0.f;
    float ssum[8];
#pragma unroll
    for (int h = 0; h < 8; h++) ssum[h] = 0.f;

    for (int k0 = 0; k0 < total; k0 += 32) {
        int kk  = k0 + lane;
        int lim = min(32, total - k0);
        __syncwarp();
        if (kk < total) {
            int srcn = (kk < deg) ? g_col[beg + kk] : node;
            float4 s0 = *(const float4*)&g_as1[srcn * 8];
            float4 s1 = *(const float4*)&g_as1[srcn * 8 + 4];
            float lg[8] = { s0.x + adr[0], s0.y + adr[1], s0.z + adr[2], s0.w + adr[3],
                            s1.x + adr[4], s1.y + adr[5], s1.z + adr[6], s1.w + adr[7] };
#pragma unroll
            for (int h = 0; h < 8; h++) {
                float wt = __expf(leaky(lg[h]));
                ssum[h] += wt;
                swt[w][h][lane] = wt;
            }
            ssrc[w][lane] = srcn;
        }
        __syncwarp();
        for (int j = 0; j < lim; j++) {
            int srcn = ssrc[w][j];
            float wt = swt[w][hl][j];
            float2 hv = *(const float2*)&g_h1[srcn * F1 + c0];
            acc0 += wt * hv.x;
            acc1 += wt * hv.y;
        }
    }
#pragma unroll
    for (int h = 0; h < 8; h++) {
#pragma unroll
        for (int off = 16; off > 0; off >>= 1)
            ssum[h] += __shfl_xor_sync(FULLM, ssum[h], off);
    }
    float myS = 0.f;
#pragma unroll
    for (int h = 0; h < 8; h++)
        if (hl == h) myS = ssum[h];
    float inv = __fdividef(1.0f, myS);

    // x2 row in registers (relu + bias)
    float v0 = fmaxf(acc0 * inv + b1[c0], 0.f);
    float v1 = fmaxf(acc1 * inv + b1[c0 + 1], 0.f);

    // fused layer-2 linear: h2 = x2 @ W2  (+ attention coefficients)
    const int cA = lane;
    const int cB = lane + 32;
    const bool has1 = (lane < 8);
    float a0 = 0.f, a1 = 0.f;
#pragma unroll
    for (int kk = 0; kk < 32; kk++) {
        float x0 = __shfl_sync(FULLM, v0, kk);
        float x1 = __shfl_sync(FULLM, v1, kk);
        a0 += x0 * sW2[(2 * kk) * C2 + cA] + x1 * sW2[(2 * kk + 1) * C2 + cA];
        if (has1)
            a1 += x0 * sW2[(2 * kk) * C2 + cB] + x1 * sW2[(2 * kk + 1) * C2 + cB];
    }
    g_h2[node * C2 + cA] = a0;
    if (has1) g_h2[node * C2 + cB] = a1;

    float ps = a0 * sAs2[cA] + (has1 ? a1 * sAs2[cB] : 0.f);
    float pd = a0 * sAd2[cA] + (has1 ? a1 * sAd2[cB] : 0.f);
#pragma unroll
    for (int off = 16; off > 0; off >>= 1) {
        ps += __shfl_xor_sync(FULLM, ps, off);
        pd += __shfl_xor_sync(FULLM, pd, off);
    }
    if (lane == 0) { g_as2[node] = ps; g_ad2[node] = pd; }
}

// ------------------------- layer-2 aggregation + bias + log_softmax (warp/node)
__global__ __launch_bounds__(256) void k_agg2(const float* __restrict__ b2,
                                              float* __restrict__ out) {
    __shared__ float swt[8][32];
    __shared__ int   ssrc[8][32];
    const int w    = threadIdx.x >> 5;
    const int lane = threadIdx.x & 31;
    const int node = blockIdx.x * 8 + w;
    if (node >= NN) return;
    const int beg   = g_rowptr[node];
    const int deg   = g_rowptr[node + 1] - beg;
    const int total = deg + 1;
    const float adn = g_ad2[node];

    const int c0 = lane;
    const int c1 = lane + 32;
    const bool has1 = (c1 < C2);
    float acc0 = 0.f, acc1 = 0.f, ssum = 0.f;
    for (int k0 = 0; k0 < total; k0 += 32) {
        int kk  = k0 + lane;
        int lim = min(32, total - k0);
        __syncwarp();
        if (kk < total) {
            int srcn = (kk < deg) ? g_col[beg + kk] : node;
            float wt = __expf(leaky(g_as2[srcn] + adn));
            ssum += wt;
            swt[w][lane]  = wt;
            ssrc[w][lane] = srcn;
        }
        __syncwarp();
        for (int j = 0; j < lim; j++) {
            int srcn = ssrc[w][j];
            float wt = swt[w][j];
            acc0 += wt * g_h2[srcn * C2 + c0];
            if (has1) acc1 += wt * g_h2[srcn * C2 + c1];
        }
    }
#pragma unroll
    for (int off = 16; off > 0; off >>= 1)
        ssum += __shfl_xor_sync(FULLM, ssum, off);
    float inv = __fdividef(1.0f, ssum);

    float o0 = acc0 * inv + b2[c0];
    float o1 = has1 ? (acc1 * inv + b2[c1]) : -1e30f;

    float mx = fmaxf(o0, o1);
#pragma unroll
    for (int off = 16; off > 0; off >>= 1)
        mx = fmaxf(mx, __shfl_xor_sync(FULLM, mx, off));
    float se = __expf(o0 - mx) + (has1 ? __expf(o1 - mx) : 0.f);
#pragma unroll
    for (int off = 16; off > 0; off >>= 1)
        se += __shfl_xor_sync(FULLM, se, off);
    float lse = mx + __logf(se);

    out[node * C2 + c0] = o0 - lse;
    if (has1) out[node * C2 + c1] = o1 - lse;
}

// ------------------------- launch (CSR build overlapped with GEMM1)
extern "C" void kernel_launch(void* const* d_in, const int* in_sizes, int n_in,
                              void* d_out, int out_size) {
    const float* x        = (const float*)d_in[0];
    const int*   ei       = (const int*)d_in[1];
    const float* W1       = (const float*)d_in[2];
    const float* att_src1 = (const float*)d_in[3];
    const float* att_dst1 = (const float*)d_in[4];
    const float* b1       = (const float*)d_in[5];
    const float* W2       = (const float*)d_in[6];
    const float* att_src2 = (const float*)d_in[7];
    const float* att_dst2 = (const float*)d_in[8];
    const float* b2       = (const float*)d_in[9];
    float* out = (float*)d_out;

    const int* src = ei;
    const int* dst = ei + EE;

    // one-time host-side resources (identical GPU work every call)
    static cudaStream_t s_csr = nullptr;
    static cudaEvent_t  e_fork = nullptr, e_join = nullptr;
    if (s_csr == nullptr) {
        cudaStreamCreateWithFlags(&s_csr, cudaStreamNonBlocking);
        cudaEventCreateWithFlags(&e_fork, cudaEventDisableTiming);
        cudaEventCreateWithFlags(&e_join, cudaEventDisableTiming);
    }

    // fork: CSR build on side stream
    cudaEventRecord(e_fork, 0);
    cudaStreamWaitEvent(s_csr, e_fork, 0);
    k_zero<<<(NN + 255) / 256, 256, 0, s_csr>>>();
    k_hist<<<(EE + 255) / 256, 256, 0, s_csr>>>(dst);
    k_part<<<NBLK, 256, 0, s_csr>>>();
    k_bscan<<<1, 256, 0, s_csr>>>();
    k_fix<<<NBLK, 256, 0, s_csr>>>();
    k_scatter<<<(EE + 255) / 256, 256, 0, s_csr>>>(src, dst);
    cudaEventRecord(e_join, s_csr);

    // concurrent: layer-1 GEMM (tf32 tensor cores + fused att coeffs)
    k_gemm1<<<(NN + 127) / 128, 256>>>(x, W1, att_src1, att_dst1);

    // join: aggregation needs both CSR and GEMM1
    cudaStreamWaitEvent(0, e_join, 0);

    // layer-1 aggregation fused with layer-2 linear + att coeffs
    k_agg1<<<(NN + 7) / 8, 256>>>(b1, W2, att_src2, att_dst2);

    // layer-2 aggregation + log_softmax
    k_agg2<<<(NN + 7) / 8, 256>>>(b2, out);
}

// round 8
// speedup vs baseline: 1.3579x; 1.0945x over previous
#include <cuda_runtime.h>
#include <cuda_fp16.h>
#include <cstdint>

#define NN   50000
#define EE   1600000
#define FIN  512
#define F1   64        // H1*C1
#define NH1  8
#define C2   40
#define NBLK 196       // ceil(NN/256)
#define FULLM 0xffffffffu

// ------------------------- scratch (static device memory; no allocs allowed)
__device__ __half g_h1h[NN * F1];      // layer1 features, fp16 (gather payload)
__device__ float  g_as1[NN * NH1];
__device__ float  g_ad1[NN * NH1];
__device__ __half g_h2h[NN * C2];      // layer2 linear out, fp16 (gather payload)
__device__ float  g_as2[NN];
__device__ float  g_ad2[NN];
__device__ int    g_deg[NN];
__device__ int    g_rowloc[NN];
__device__ int    g_bsum[256];
__device__ int    g_boff[256];
__device__ int    g_rowptr[NN + 1];
__device__ int    g_cursor[NN];
__device__ int    g_col[EE];

__device__ __forceinline__ float leaky(float v) { return v > 0.f ? v : 0.2f * v; }

__device__ __forceinline__ uint32_t f2tf(float f) {
    uint32_t u;
    asm("cvt.rna.tf32.f32 %0, %1;" : "=r"(u) : "f"(f));
    return u;
}

__device__ __forceinline__ void mma_tf32(float* d, const uint32_t* a, const uint32_t* b) {
    asm volatile(
        "mma.sync.aligned.m16n8k8.row.col.f32.tf32.tf32.f32 "
        "{%0,%1,%2,%3}, {%4,%5,%6,%7}, {%8,%9}, {%0,%1,%2,%3};"
        : "+f"(d[0]), "+f"(d[1]), "+f"(d[2]), "+f"(d[3])
        : "r"(a[0]), "r"(a[1]), "r"(a[2]), "r"(a[3]), "r"(b[0]), "r"(b[1]));
}

// ------------------------- GEMM1 (tf32 tensor cores) + fused attention coeffs
__global__ __launch_bounds__(256) void k_gemm1(const float* __restrict__ x,
                                               const float* __restrict__ W1,
                                               const float* __restrict__ attS,
                                               const float* __restrict__ attD) {
    __shared__ float sA[128][36];
    __shared__ float sB[32][72];
    __shared__ float sAs[64], sAd[64];

    const int t    = threadIdx.x;
    const int wid  = t >> 5;
    const int lane = t & 31;
    const int m0   = blockIdx.x * 128;
    const int warp_m = (wid >> 1) * 32;
    const int warp_n = (wid & 1) * 32;
    if (t < 64) { sAs[t] = attS[t]; sAd[t] = attD[t]; }

    float acc[2][4][4];
#pragma unroll
    for (int mi = 0; mi < 2; mi++)
#pragma unroll
        for (int ni = 0; ni < 4; ni++)
#pragma unroll
            for (int e = 0; e < 4; e++) acc[mi][ni][e] = 0.f;

    const int r = lane >> 2;
    const int c = lane & 3;
    const int arow = t >> 3;
    const int acol = (t & 7) * 4;

    for (int kc = 0; kc < FIN; kc += 32) {
#pragma unroll
        for (int i = 0; i < 4; i++) {
            int row = i * 32 + arow;
            int gm  = m0 + row;
            float4 v = (gm < NN) ? *(const float4*)&x[(long)gm * FIN + kc + acol]
                                 : make_float4(0.f, 0.f, 0.f, 0.f);
            float4 tv;
            tv.x = __uint_as_float(f2tf(v.x));
            tv.y = __uint_as_float(f2tf(v.y));
            tv.z = __uint_as_float(f2tf(v.z));
            tv.w = __uint_as_float(f2tf(v.w));
            *(float4*)&sA[row][acol] = tv;
        }
#pragma unroll
        for (int i = 0; i < 2; i++) {
            int f   = t + i * 256;
            int row = f >> 4;
            int c4  = (f & 15) * 4;
            float4 v = *(const float4*)&W1[(kc + row) * F1 + c4];
            float4 tv;
            tv.x = __uint_as_float(f2tf(v.x));
            tv.y = __uint_as_float(f2tf(v.y));
            tv.z = __uint_as_float(f2tf(v.z));
            tv.w = __uint_as_float(f2tf(v.w));
            *(float4*)&sB[row][c4] = tv;
        }
        __syncthreads();

#pragma unroll
        for (int ks = 0; ks < 4; ks++) {
            const int k0 = ks * 8;
            uint32_t afrag[2][4];
#pragma unroll
            for (int mi = 0; mi < 2; mi++) {
                int mm = warp_m + mi * 16;
                afrag[mi][0] = __float_as_uint(sA[mm + r][k0 + c]);
                afrag[mi][1] = __float_as_uint(sA[mm + r + 8][k0 + c]);
                afrag[mi][2] = __float_as_uint(sA[mm + r][k0 + c + 4]);
                afrag[mi][3] = __float_as_uint(sA[mm + r + 8][k0 + c + 4]);
            }
            uint32_t bfrag[4][2];
#pragma unroll
            for (int ni = 0; ni < 4; ni++) {
                int nn = warp_n + ni * 8;
                bfrag[ni][0] = __float_as_uint(sB[k0 + c][nn + r]);
                bfrag[ni][1] = __float_as_uint(sB[k0 + c + 4][nn + r]);
            }
#pragma unroll
            for (int mi = 0; mi < 2; mi++)
#pragma unroll
                for (int ni = 0; ni < 4; ni++)
                    mma_tf32(acc[mi][ni], afrag[mi], bfrag[ni]);
        }
        __syncthreads();
    }

#pragma unroll
    for (int mi = 0; mi < 2; mi++) {
        int row_g = m0 + warp_m + mi * 16 + r;
        int row_h = row_g + 8;
#pragma unroll
        for (int ni = 0; ni < 4; ni++) {
            int nn = warp_n + ni * 8;
            int col = nn + c * 2;
            if (row_g < NN)
                *(__half2*)&g_h1h[row_g * F1 + col] = __floats2half2_rn(acc[mi][ni][0], acc[mi][ni][1]);
            if (row_h < NN)
                *(__half2*)&g_h1h[row_h * F1 + col] = __floats2half2_rn(acc[mi][ni][2], acc[mi][ni][3]);
            float as0 = sAs[col], as1v = sAs[col + 1];
            float ad0 = sAd[col], ad1v = sAd[col + 1];
            float psg = acc[mi][ni][0] * as0 + acc[mi][ni][1] * as1v;
            float pdg = acc[mi][ni][0] * ad0 + acc[mi][ni][1] * ad1v;
            float psh = acc[mi][ni][2] * as0 + acc[mi][ni][3] * as1v;
            float pdh = acc[mi][ni][2] * ad0 + acc[mi][ni][3] * ad1v;
#pragma unroll
            for (int off = 1; off <= 2; off <<= 1) {
                psg += __shfl_xor_sync(FULLM, psg, off);
                pdg += __shfl_xor_sync(FULLM, pdg, off);
                psh += __shfl_xor_sync(FULLM, psh, off);
                pdh += __shfl_xor_sync(FULLM, pdh, off);
            }
            int h = nn >> 3;
            if (c == 0) {
                if (row_g < NN) { g_as1[row_g * NH1 + h] = psg; g_ad1[row_g * NH1 + h] = pdg; }
                if (row_h < NN) { g_as1[row_h * NH1 + h] = psh; g_ad1[row_h * NH1 + h] = pdh; }
            }
        }
    }
}

// ------------------------- CSR build
__global__ void k_zero() {
    int i = blockIdx.x * blockDim.x + threadIdx.x;
    if (i < NN) g_deg[i] = 0;
}
__global__ void k_hist(const int* __restrict__ dst) {
    int e = blockIdx.x * blockDim.x + threadIdx.x;
    if (e < EE) atomicAdd(&g_deg[dst[e]], 1);
}
__global__ __launch_bounds__(256) void k_part() {
    __shared__ int sm[256];
    int t = threadIdx.x, i = blockIdx.x * 256 + t;
    int d = (i < NN) ? g_deg[i] : 0;
    sm[t] = d;
    __syncthreads();
#pragma unroll
    for (int off = 1; off < 256; off <<= 1) {
        int v = (t >= off) ? sm[t - off] : 0;
        __syncthreads();
        sm[t] += v;
        __syncthreads();
    }
    if (i < NN) g_rowloc[i] = sm[t] - d;
    if (t == 255) g_bsum[blockIdx.x] = sm[255];
}
__global__ __launch_bounds__(256) void k_bscan() {
    __shared__ int sm[256];
    int t = threadIdx.x;
    int d = (t < NBLK) ? g_bsum[t] : 0;
    sm[t] = d;
    __syncthreads();
#pragma unroll
    for (int off = 1; off < 256; off <<= 1) {
        int v = (t >= off) ? sm[t - off] : 0;
        __syncthreads();
        sm[t] += v;
        __syncthreads();
    }
    if (t < NBLK) g_boff[t] = sm[t] - d;
    if (t == NBLK - 1) g_rowptr[NN] = sm[t];
}
__global__ void k_fix() {
    int i = blockIdx.x * blockDim.x + threadIdx.x;
    if (i < NN) {
        int rp = g_rowloc[i] + g_boff[blockIdx.x];
        g_rowptr[i] = rp;
        g_cursor[i] = rp;
    }
}
__global__ void k_scatter(const int* __restrict__ src, const int* __restrict__ dst) {
    int e = blockIdx.x * blockDim.x + threadIdx.x;
    if (e < EE) {
        int d = dst[e];
        int p = atomicAdd(&g_cursor[d], 1);
        g_col[p] = src[e];
    }
}

// ------------------------- layer-1 aggregation + fused layer-2 linear/att
// one warp per dst node; fp16 feature gathers, fp32 math
__global__ __launch_bounds__(256) void k_agg1(const float* __restrict__ b1,
                                              const float* __restrict__ W2,
                                              const float* __restrict__ att_s,
                                              const float* __restrict__ att_d) {
    __shared__ float swt[8][8][36];
    __shared__ int   ssrc[8][32];
    __shared__ float sW2[F1 * C2];
    __shared__ float sAs2[C2], sAd2[C2];

    for (int idx = threadIdx.x; idx < F1 * C2; idx += 256) sW2[idx] = W2[idx];
    if (threadIdx.x < C2) {
        sAs2[threadIdx.x] = att_s[threadIdx.x];
        sAd2[threadIdx.x] = att_d[threadIdx.x];
    }
    __syncthreads();

    const int w    = threadIdx.x >> 5;
    const int lane = threadIdx.x & 31;
    const int node = blockIdx.x * 8 + w;
    if (node >= NN) return;
    const int beg   = g_rowptr[node];
    const int deg   = g_rowptr[node + 1] - beg;
    const int total = deg + 1;

    float4 ad0 = *(const float4*)&g_ad1[node * 8];
    float4 ad1 = *(const float4*)&g_ad1[node * 8 + 4];
    float adr[8] = { ad0.x, ad0.y, ad0.z, ad0.w, ad1.x, ad1.y, ad1.z, ad1.w };

    const int hl = lane >> 2;
    const int c0 = lane * 2;
    float acc0 = 0.f, acc1 = 0.f;
    float ssum[8];
#pragma unroll
    for (int h = 0; h < 8; h++) ssum[h] = 0.f;

    for (int k0 = 0; k0 < total; k0 += 32) {
        int kk  = k0 + lane;
        int lim = min(32, total - k0);
        __syncwarp();
        if (kk < total) {
            int srcn = (kk < deg) ? g_col[beg + kk] : node;
            float4 s0 = *(const float4*)&g_as1[srcn * 8];
            float4 s1 = *(const float4*)&g_as1[srcn * 8 + 4];
            float lg[8] = { s0.x + adr[0], s0.y + adr[1], s0.z + adr[2], s0.w + adr[3],
                            s1.x + adr[4], s1.y + adr[5], s1.z + adr[6], s1.w + adr[7] };
#pragma unroll
            for (int h = 0; h < 8; h++) {
                float wt = __expf(leaky(lg[h]));
                ssum[h] += wt;
                swt[w][h][lane] = wt;
            }
            ssrc[w][lane] = srcn;
        }
        __syncwarp();
        for (int j = 0; j < lim; j++) {
            int srcn = ssrc[w][j];
            float wt = swt[w][hl][j];
            float2 hv = __half22float2(*(const __half2*)&g_h1h[srcn * F1 + c0]);
            acc0 += wt * hv.x;
            acc1 += wt * hv.y;
        }
    }
#pragma unroll
    for (int h = 0; h < 8; h++) {
#pragma unroll
        for (int off = 16; off > 0; off >>= 1)
            ssum[h] += __shfl_xor_sync(FULLM, ssum[h], off);
    }
    float myS = 0.f;
#pragma unroll
    for (int h = 0; h < 8; h++)
        if (hl == h) myS = ssum[h];
    float inv = __fdividef(1.0f, myS);

    // x2 row in registers (relu + bias)
    float v0 = fmaxf(acc0 * inv + b1[c0], 0.f);
    float v1 = fmaxf(acc1 * inv + b1[c0 + 1], 0.f);

    // fused layer-2 linear: h2 = x2 @ W2  (+ attention coefficients)
    const int cA = lane;
    const int cB = lane + 32;
    const bool has1 = (lane < 8);
    float a0 = 0.f, a1 = 0.f;
#pragma unroll
    for (int kk = 0; kk < 32; kk++) {
        float x0 = __shfl_sync(FULLM, v0, kk);
        float x1 = __shfl_sync(FULLM, v1, kk);
        a0 += x0 * sW2[(2 * kk) * C2 + cA] + x1 * sW2[(2 * kk + 1) * C2 + cA];
        if (has1)
            a1 += x0 * sW2[(2 * kk) * C2 + cB] + x1 * sW2[(2 * kk + 1) * C2 + cB];
    }
    g_h2h[node * C2 + cA] = __float2half_rn(a0);
    if (has1) g_h2h[node * C2 + cB] = __float2half_rn(a1);

    float ps = a0 * sAs2[cA] + (has1 ? a1 * sAs2[cB] : 0.f);
    float pd = a0 * sAd2[cA] + (has1 ? a1 * sAd2[cB] : 0.f);
#pragma unroll
    for (int off = 16; off > 0; off >>= 1) {
        ps += __shfl_xor_sync(FULLM, ps, off);
        pd += __shfl_xor_sync(FULLM, pd, off);
    }
    if (lane == 0) { g_as2[node] = ps; g_ad2[node] = pd; }
}

// ------------------------- layer-2 aggregation + bias + log_softmax
// one warp per node; 20 lanes own channel PAIRS (half2 loads)
__global__ __launch_bounds__(256) void k_agg2(const float* __restrict__ b2,
                                              float* __restrict__ out) {
    __shared__ float swt[8][32];
    __shared__ int   ssrc[8][32];
    const int w    = threadIdx.x >> 5;
    const int lane = threadIdx.x & 31;
    const int node = blockIdx.x * 8 + w;
    if (node >= NN) return;
    const int beg   = g_rowptr[node];
    const int deg   = g_rowptr[node + 1] - beg;
    const int total = deg + 1;
    const float adn = g_ad2[node];

    const bool active = (lane < 20);        // channel pair 2*lane, 2*lane+1
    const int cp = lane * 2;
    float acc0 = 0.f, acc1 = 0.f, ssum = 0.f;
    for (int k0 = 0; k0 < total; k0 += 32) {
        int kk  = k0 + lane;
        int lim = min(32, total - k0);
        __syncwarp();
        if (kk < total) {
            int srcn = (kk < deg) ? g_col[beg + kk] : node;
            float wt = __expf(leaky(g_as2[srcn] + adn));
            ssum += wt;
            swt[w][lane]  = wt;
            ssrc[w][lane] = srcn;
        }
        __syncwarp();
        if (active) {
            for (int j = 0; j < lim; j++) {
                int srcn = ssrc[w][j];
                float wt = swt[w][j];
                float2 hv = __half22float2(*(const __half2*)&g_h2h[srcn * C2 + cp]);
                acc0 += wt * hv.x;
                acc1 += wt * hv.y;
            }
        }
    }
#pragma unroll
    for (int off = 16; off > 0; off >>= 1)
        ssum += __shfl_xor_sync(FULLM, ssum, off);
    float inv = __fdividef(1.0f, ssum);

    float o0 = active ? (acc0 * inv + b2[cp])     : -1e30f;
    float o1 = active ? (acc1 * inv + b2[cp + 1]) : -1e30f;

    float mx = fmaxf(o0, o1);
#pragma unroll
    for (int off = 16; off > 0; off >>= 1)
        mx = fmaxf(mx, __shfl_xor_sync(FULLM, mx, off));
    float se = active ? (__expf(o0 - mx) + __expf(o1 - mx)) : 0.f;
#pragma unroll
    for (int off = 16; off > 0; off >>= 1)
        se += __shfl_xor_sync(FULLM, se, off);
    float lse = mx + __logf(se);

    if (active)
        *(float2*)&out[node * C2 + cp] = make_float2(o0 - lse, o1 - lse);
}

// ------------------------- launch (CSR build overlapped with GEMM1)
extern "C" void kernel_launch(void* const* d_in, const int* in_sizes, int n_in,
                              void* d_out, int out_size) {
    const float* x        = (const float*)d_in[0];
    const int*   ei       = (const int*)d_in[1];
    const float* W1       = (const float*)d_in[2];
    const float* att_src1 = (const float*)d_in[3];
    const float* att_dst1 = (const float*)d_in[4];
    const float* b1       = (const float*)d_in[5];
    const float* W2       = (const float*)d_in[6];
    const float* att_src2 = (const float*)d_in[7];
    const float* att_dst2 = (const float*)d_in[8];
    const float* b2       = (const float*)d_in[9];
    float* out = (float*)d_out;

    const int* src = ei;
    const int* dst = ei + EE;

    // one-time host-side resources (identical GPU work every call)
    static cudaStream_t s_csr = nullptr;
    static cudaEvent_t  e_fork = nullptr, e_join = nullptr;
    if (s_csr == nullptr) {
        cudaStreamCreateWithFlags(&s_csr, cudaStreamNonBlocking);
        cudaEventCreateWithFlags(&e_fork, cudaEventDisableTiming);
        cudaEventCreateWithFlags(&e_join, cudaEventDisableTiming);
    }

    // fork: CSR build on side stream
    cudaEventRecord(e_fork, 0);
    cudaStreamWaitEvent(s_csr, e_fork, 0);
    k_zero<<<(NN + 255) / 256, 256, 0, s_csr>>>();
    k_hist<<<(EE + 255) / 256, 256, 0, s_csr>>>(dst);
    k_part<<<NBLK, 256, 0, s_csr>>>();
    k_bscan<<<1, 256, 0, s_csr>>>();
    k_fix<<<NBLK, 256, 0, s_csr>>>();
    k_scatter<<<(EE + 255) / 256, 256, 0, s_csr>>>(src, dst);
    cudaEventRecord(e_join, s_csr);

    // concurrent: layer-1 GEMM (tf32 tensor cores + fused att coeffs)
    k_gemm1<<<(NN + 127) / 128, 256>>>(x, W1, att_src1, att_dst1);

    // join: aggregation needs both CSR and GEMM1
    cudaStreamWaitEvent(0, e_join, 0);

    // layer-1 aggregation fused with layer-2 linear + att coeffs
    k_agg1<<<(NN + 7) / 8, 256>>>(b1, W2, att_src2, att_dst2);

    // layer-2 aggregation + log_softmax
    k_agg2<<<(NN + 7) / 8, 256>>>(b2, out);
}

// round 9
// speedup vs baseline: 1.3738x; 1.0117x over previous
#include <cuda_runtime.h>
#include <cuda_fp16.h>
#include <cstdint>

#define NN   50000
#define EE   1600000
#define FIN  512
#define F1   64        // H1*C1
#define NH1  8
#define C2   40
#define NBLK 196       // ceil(NN/256)
#define FULLM 0xffffffffu
#define LOG2E 1.4426950408889634f

// ------------------------- scratch (static device memory; no allocs allowed)
__device__ __half g_h1h[NN * F1];      // layer1 features, fp16 (gather payload)
__device__ __half g_as1h[NN * NH1];    // alpha_src1 * log2e, fp16
__device__ __half g_ad1h[NN * NH1];    // alpha_dst1 * log2e, fp16
__device__ __half g_h2h[NN * C2];      // layer2 linear out, fp16 (gather payload)
__device__ float  g_as2[NN];
__device__ float  g_ad2[NN];
__device__ int    g_deg[NN];
__device__ int    g_rowloc[NN];
__device__ int    g_bsum[256];
__device__ int    g_boff[256];
__device__ int    g_rowptr[NN + 1];
__device__ int    g_cursor[NN];
__device__ int    g_col[EE];

__device__ __forceinline__ float leaky(float v) { return v > 0.f ? v : 0.2f * v; }

__device__ __forceinline__ uint32_t f2tf(float f) {
    uint32_t u;
    asm("cvt.rna.tf32.f32 %0, %1;" : "=r"(u) : "f"(f));
    return u;
}

__device__ __forceinline__ void mma_tf32(float* d, const uint32_t* a, const uint32_t* b) {
    asm volatile(
        "mma.sync.aligned.m16n8k8.row.col.f32.tf32.tf32.f32 "
        "{%0,%1,%2,%3}, {%4,%5,%6,%7}, {%8,%9}, {%0,%1,%2,%3};"
        : "+f"(d[0]), "+f"(d[1]), "+f"(d[2]), "+f"(d[3])
        : "r"(a[0]), "r"(a[1]), "r"(a[2]), "r"(a[3]), "r"(b[0]), "r"(b[1]));
}

__device__ __forceinline__ __half2 h2ex2(__half2 x) {
    __half2 r;
    asm("ex2.approx.f16x2 %0, %1;"
        : "=r"(*(uint32_t*)&r) : "r"(*(uint32_t*)&x));
    return r;
}
__device__ __forceinline__ __half2 u2h2(uint32_t u) { return *(__half2*)&u; }

// ------------------------- GEMM1 (tf32 tensor cores) + fused attention coeffs
__global__ __launch_bounds__(256) void k_gemm1(const float* __restrict__ x,
                                               const float* __restrict__ W1,
                                               const float* __restrict__ attS,
                                               const float* __restrict__ attD) {
    __shared__ float sA[128][36];
    __shared__ float sB[32][72];
    __shared__ float sAs[64], sAd[64];

    const int t    = threadIdx.x;
    const int wid  = t >> 5;
    const int lane = t & 31;
    const int m0   = blockIdx.x * 128;
    const int warp_m = (wid >> 1) * 32;
    const int warp_n = (wid & 1) * 32;
    if (t < 64) { sAs[t] = attS[t]; sAd[t] = attD[t]; }

    float acc[2][4][4];
#pragma unroll
    for (int mi = 0; mi < 2; mi++)
#pragma unroll
        for (int ni = 0; ni < 4; ni++)
#pragma unroll
            for (int e = 0; e < 4; e++) acc[mi][ni][e] = 0.f;

    const int r = lane >> 2;
    const int c = lane & 3;
    const int arow = t >> 3;
    const int acol = (t & 7) * 4;

    for (int kc = 0; kc < FIN; kc += 32) {
#pragma unroll
        for (int i = 0; i < 4; i++) {
            int row = i * 32 + arow;
            int gm  = m0 + row;
            float4 v = (gm < NN) ? *(const float4*)&x[(long)gm * FIN + kc + acol]
                                 : make_float4(0.f, 0.f, 0.f, 0.f);
            float4 tv;
            tv.x = __uint_as_float(f2tf(v.x));
            tv.y = __uint_as_float(f2tf(v.y));
            tv.z = __uint_as_float(f2tf(v.z));
            tv.w = __uint_as_float(f2tf(v.w));
            *(float4*)&sA[row][acol] = tv;
        }
#pragma unroll
        for (int i = 0; i < 2; i++) {
            int f   = t + i * 256;
            int row = f >> 4;
            int c4  = (f & 15) * 4;
            float4 v = *(const float4*)&W1[(kc + row) * F1 + c4];
            float4 tv;
            tv.x = __uint_as_float(f2tf(v.x));
            tv.y = __uint_as_float(f2tf(v.y));
            tv.z = __uint_as_float(f2tf(v.z));
            tv.w = __uint_as_float(f2tf(v.w));
            *(float4*)&sB[row][c4] = tv;
        }
        __syncthreads();

#pragma unroll
        for (int ks = 0; ks < 4; ks++) {
            const int k0 = ks * 8;
            uint32_t afrag[2][4];
#pragma unroll
            for (int mi = 0; mi < 2; mi++) {
                int mm = warp_m + mi * 16;
                afrag[mi][0] = __float_as_uint(sA[mm + r][k0 + c]);
                afrag[mi][1] = __float_as_uint(sA[mm + r + 8][k0 + c]);
                afrag[mi][2] = __float_as_uint(sA[mm + r][k0 + c + 4]);
                afrag[mi][3] = __float_as_uint(sA[mm + r + 8][k0 + c + 4]);
            }
            uint32_t bfrag[4][2];
#pragma unroll
            for (int ni = 0; ni < 4; ni++) {
                int nn = warp_n + ni * 8;
                bfrag[ni][0] = __float_as_uint(sB[k0 + c][nn + r]);
                bfrag[ni][1] = __float_as_uint(sB[k0 + c + 4][nn + r]);
            }
#pragma unroll
            for (int mi = 0; mi < 2; mi++)
#pragma unroll
                for (int ni = 0; ni < 4; ni++)
                    mma_tf32(acc[mi][ni], afrag[mi], bfrag[ni]);
        }
        __syncthreads();
    }

#pragma unroll
    for (int mi = 0; mi < 2; mi++) {
        int row_g = m0 + warp_m + mi * 16 + r;
        int row_h = row_g + 8;
#pragma unroll
        for (int ni = 0; ni < 4; ni++) {
            int nn = warp_n + ni * 8;
            int col = nn + c * 2;
            if (row_g < NN)
                *(__half2*)&g_h1h[row_g * F1 + col] = __floats2half2_rn(acc[mi][ni][0], acc[mi][ni][1]);
            if (row_h < NN)
                *(__half2*)&g_h1h[row_h * F1 + col] = __floats2half2_rn(acc[mi][ni][2], acc[mi][ni][3]);
            float as0 = sAs[col], as1v = sAs[col + 1];
            float ad0 = sAd[col], ad1v = sAd[col + 1];
            float psg = acc[mi][ni][0] * as0 + acc[mi][ni][1] * as1v;
            float pdg = acc[mi][ni][0] * ad0 + acc[mi][ni][1] * ad1v;
            float psh = acc[mi][ni][2] * as0 + acc[mi][ni][3] * as1v;
            float pdh = acc[mi][ni][2] * ad0 + acc[mi][ni][3] * ad1v;
#pragma unroll
            for (int off = 1; off <= 2; off <<= 1) {
                psg += __shfl_xor_sync(FULLM, psg, off);
                pdg += __shfl_xor_sync(FULLM, pdg, off);
                psh += __shfl_xor_sync(FULLM, psh, off);
                pdh += __shfl_xor_sync(FULLM, pdh, off);
            }
            int h = nn >> 3;
            if (c == 0) {
                if (row_g < NN) {
                    g_as1h[row_g * NH1 + h] = __float2half_rn(psg * LOG2E);
                    g_ad1h[row_g * NH1 + h] = __float2half_rn(pdg * LOG2E);
                }
                if (row_h < NN) {
                    g_as1h[row_h * NH1 + h] = __float2half_rn(psh * LOG2E);
                    g_ad1h[row_h * NH1 + h] = __float2half_rn(pdh * LOG2E);
                }
            }
        }
    }
}

// ------------------------- CSR build
__global__ void k_zero() {
    int i = blockIdx.x * blockDim.x + threadIdx.x;
    if (i < NN) g_deg[i] = 0;
}
__global__ void k_hist(const int* __restrict__ dst) {
    int e = blockIdx.x * blockDim.x + threadIdx.x;
    if (e < EE) atomicAdd(&g_deg[dst[e]], 1);
}
__global__ __launch_bounds__(256) void k_part() {
    __shared__ int sm[256];
    int t = threadIdx.x, i = blockIdx.x * 256 + t;
    int d = (i < NN) ? g_deg[i] : 0;
    sm[t] = d;
    __syncthreads();
#pragma unroll
    for (int off = 1; off < 256; off <<= 1) {
        int v = (t >= off) ? sm[t - off] : 0;
        __syncthreads();
        sm[t] += v;
        __syncthreads();
    }
    if (i < NN) g_rowloc[i] = sm[t] - d;
    if (t == 255) g_bsum[blockIdx.x] = sm[255];
}
__global__ __launch_bounds__(256) void k_bscan() {
    __shared__ int sm[256];
    int t = threadIdx.x;
    int d = (t < NBLK) ? g_bsum[t] : 0;
    sm[t] = d;
    __syncthreads();
#pragma unroll
    for (int off = 1; off < 256; off <<= 1) {
        int v = (t >= off) ? sm[t - off] : 0;
        __syncthreads();
        sm[t] += v;
        __syncthreads();
    }
    if (t < NBLK) g_boff[t] = sm[t] - d;
    if (t == NBLK - 1) g_rowptr[NN] = sm[t];
}
__global__ void k_fix() {
    int i = blockIdx.x * blockDim.x + threadIdx.x;
    if (i < NN) {
        int rp = g_rowloc[i] + g_boff[blockIdx.x];
        g_rowptr[i] = rp;
        g_cursor[i] = rp;
    }
}
__global__ void k_scatter(const int* __restrict__ src, const int* __restrict__ dst) {
    int e = blockIdx.x * blockDim.x + threadIdx.x;
    if (e < EE) {
        int d = dst[e];
        int p = atomicAdd(&g_cursor[d], 1);
        g_col[p] = src[e];
    }
}

// ------------------------- layer-1 aggregation + fused layer-2 linear/att
// one warp per dst node; f16x2 logits + ex2.approx.f16x2 (2 heads/MUFU op)
__global__ __launch_bounds__(256) void k_agg1(const float* __restrict__ b1,
                                              const float* __restrict__ W2,
                                              const float* __restrict__ att_s,
                                              const float* __restrict__ att_d) {
    __shared__ float swt[8][8][36];
    __shared__ int   ssrc[8][32];
    __shared__ float sW2[F1 * C2];
    __shared__ float sAs2[C2], sAd2[C2];

    for (int idx = threadIdx.x; idx < F1 * C2; idx += 256) sW2[idx] = W2[idx];
    if (threadIdx.x < C2) {
        sAs2[threadIdx.x] = att_s[threadIdx.x];
        sAd2[threadIdx.x] = att_d[threadIdx.x];
    }
    __syncthreads();

    const int w    = threadIdx.x >> 5;
    const int lane = threadIdx.x & 31;
    const int node = blockIdx.x * 8 + w;
    if (node >= NN) return;
    const int beg   = g_rowptr[node];
    const int deg   = g_rowptr[node + 1] - beg;
    const int total = deg + 1;

    const __half2 k02 = __floats2half2_rn(0.2f, 0.2f);
    int4 adv = *(const int4*)&g_ad1h[node * NH1];
    __half2 adp[4] = { u2h2(adv.x), u2h2(adv.y), u2h2(adv.z), u2h2(adv.w) };

    const int hl = lane >> 2;
    const int c0 = lane * 2;
    float acc0 = 0.f, acc1 = 0.f;
    float ssum[8];
#pragma unroll
    for (int h = 0; h < 8; h++) ssum[h] = 0.f;

    for (int k0 = 0; k0 < total; k0 += 32) {
        int kk  = k0 + lane;
        int lim = min(32, total - k0);
        __syncwarp();
        if (kk < total) {
            int srcn = (kk < deg) ? g_col[beg + kk] : node;
            int4 sv = *(const int4*)&g_as1h[srcn * NH1];
            __half2 sp[4] = { u2h2(sv.x), u2h2(sv.y), u2h2(sv.z), u2h2(sv.w) };
#pragma unroll
            for (int p = 0; p < 4; p++) {
                __half2 l = __hadd2(sp[p], adp[p]);                  // (as+ad)*log2e
                __half2 lk = __hmax2(l, __hmul2(l, k02));            // leaky (exact)
                float2 f = __half22float2(h2ex2(lk));                // exp via ex2
                ssum[2 * p]     += f.x;
                ssum[2 * p + 1] += f.y;
                swt[w][2 * p][lane]     = f.x;
                swt[w][2 * p + 1][lane] = f.y;
            }
            ssrc[w][lane] = srcn;
        }
        __syncwarp();
        for (int j = 0; j < lim; j++) {
            int srcn = ssrc[w][j];
            float wt = swt[w][hl][j];
            float2 hv = __half22float2(*(const __half2*)&g_h1h[srcn * F1 + c0]);
            acc0 += wt * hv.x;
            acc1 += wt * hv.y;
        }
    }
#pragma unroll
    for (int h = 0; h < 8; h++) {
#pragma unroll
        for (int off = 16; off > 0; off >>= 1)
            ssum[h] += __shfl_xor_sync(FULLM, ssum[h], off);
    }
    float myS = 0.f;
#pragma unroll
    for (int h = 0; h < 8; h++)
        if (hl == h) myS = ssum[h];
    float inv = __fdividef(1.0f, myS);

    // x2 row in registers (relu + bias)
    float v0 = fmaxf(acc0 * inv + b1[c0], 0.f);
    float v1 = fmaxf(acc1 * inv + b1[c0 + 1], 0.f);

    // fused layer-2 linear: h2 = x2 @ W2  (+ attention coefficients)
    const int cA = lane;
    const int cB = lane + 32;
    const bool has1 = (lane < 8);
    float a0 = 0.f, a1 = 0.f;
#pragma unroll
    for (int kk = 0; kk < 32; kk++) {
        float x0 = __shfl_sync(FULLM, v0, kk);
        float x1 = __shfl_sync(FULLM, v1, kk);
        a0 += x0 * sW2[(2 * kk) * C2 + cA] + x1 * sW2[(2 * kk + 1) * C2 + cA];
        if (has1)
            a1 += x0 * sW2[(2 * kk) * C2 + cB] + x1 * sW2[(2 * kk + 1) * C2 + cB];
    }
    g_h2h[node * C2 + cA] = __float2half_rn(a0);
    if (has1) g_h2h[node * C2 + cB] = __float2half_rn(a1);

    float ps = a0 * sAs2[cA] + (has1 ? a1 * sAs2[cB] : 0.f);
    float pd = a0 * sAd2[cA] + (has1 ? a1 * sAd2[cB] : 0.f);
#pragma unroll
    for (int off = 16; off > 0; off >>= 1) {
        ps += __shfl_xor_sync(FULLM, ps, off);
        pd += __shfl_xor_sync(FULLM, pd, off);
    }
    if (lane == 0) { g_as2[node] = ps; g_ad2[node] = pd; }
}

// ------------------------- layer-2 aggregation + bias + log_softmax
// one warp per node; 20 lanes own channel PAIRS (half2 loads)
__global__ __launch_bounds__(256) void k_agg2(const float* __restrict__ b2,
                                              float* __restrict__ out) {
    __shared__ float swt[8][32];
    __shared__ int   ssrc[8][32];
    const int w    = threadIdx.x >> 5;
    const int lane = threadIdx.x & 31;
    const int node = blockIdx.x * 8 + w;
    if (node >= NN) return;
    const int beg   = g_rowptr[node];
    const int deg   = g_rowptr[node + 1] - beg;
    const int total = deg + 1;
    const float adn = g_ad2[node];

    const bool active = (lane < 20);        // channel pair 2*lane, 2*lane+1
    const int cp = lane * 2;
    float acc0 = 0.f, acc1 = 0.f, ssum = 0.f;
    for (int k0 = 0; k0 < total; k0 += 32) {
        int kk  = k0 + lane;
        int lim = min(32, total - k0);
        __syncwarp();
        if (kk < total) {
            int srcn = (kk < deg) ? g_col[beg + kk] : node;
            float wt = __expf(leaky(g_as2[srcn] + adn));
            ssum += wt;
            swt[w][lane]  = wt;
            ssrc[w][lane] = srcn;
        }
        __syncwarp();
        if (active) {
            for (int j = 0; j < lim; j++) {
                int srcn = ssrc[w][j];
                float wt = swt[w][j];
                float2 hv = __half22float2(*(const __half2*)&g_h2h[srcn * C2 + cp]);
                acc0 += wt * hv.x;
                acc1 += wt * hv.y;
            }
        }
    }
#pragma unroll
    for (int off = 16; off > 0; off >>= 1)
        ssum += __shfl_xor_sync(FULLM, ssum, off);
    float inv = __fdividef(1.0f, ssum);

    float o0 = active ? (acc0 * inv + b2[cp])     : -1e30f;
    float o1 = active ? (acc1 * inv + b2[cp + 1]) : -1e30f;

    float mx = fmaxf(o0, o1);
#pragma unroll
    for (int off = 16; off > 0; off >>= 1)
        mx = fmaxf(mx, __shfl_xor_sync(FULLM, mx, off));
    float se = active ? (__expf(o0 - mx) + __expf(o1 - mx)) : 0.f;
#pragma unroll
    for (int off = 16; off > 0; off >>= 1)
        se += __shfl_xor_sync(FULLM, se, off);
    float lse = mx + __logf(se);

    if (active)
        *(float2*)&out[node * C2 + cp] = make_float2(o0 - lse, o1 - lse);
}

// ------------------------- launch (CSR build overlapped with GEMM1)
extern "C" void kernel_launch(void* const* d_in, const int* in_sizes, int n_in,
                              void* d_out, int out_size) {
    const float* x        = (const float*)d_in[0];
    const int*   ei       = (const int*)d_in[1];
    const float* W1       = (const float*)d_in[2];
    const float* att_src1 = (const float*)d_in[3];
    const float* att_dst1 = (const float*)d_in[4];
    const float* b1       = (const float*)d_in[5];
    const float* W2       = (const float*)d_in[6];
    const float* att_src2 = (const float*)d_in[7];
    const float* att_dst2 = (const float*)d_in[8];
    const float* b2       = (const float*)d_in[9];
    float* out = (float*)d_out;

    const int* src = ei;
    const int* dst = ei + EE;

    // one-time host-side resources (identical GPU work every call)
    static cudaStream_t s_csr = nullptr;
    static cudaEvent_t  e_fork = nullptr, e_join = nullptr;
    if (s_csr == nullptr) {
        cudaStreamCreateWithFlags(&s_csr, cudaStreamNonBlocking);
        cudaEventCreateWithFlags(&e_fork, cudaEventDisableTiming);
        cudaEventCreateWithFlags(&e_join, cudaEventDisableTiming);
    }

    // fork: CSR build on side stream
    cudaEventRecord(e_fork, 0);
    cudaStreamWaitEvent(s_csr, e_fork, 0);
    k_zero<<<(NN + 255) / 256, 256, 0, s_csr>>>();
    k_hist<<<(EE + 255) / 256, 256, 0, s_csr>>>(dst);
    k_part<<<NBLK, 256, 0, s_csr>>>();
    k_bscan<<<1, 256, 0, s_csr>>>();
    k_fix<<<NBLK, 256, 0, s_csr>>>();
    k_scatter<<<(EE + 255) / 256, 256, 0, s_csr>>>(src, dst);
    cudaEventRecord(e_join, s_csr);

    // concurrent: layer-1 GEMM (tf32 tensor cores + fused att coeffs)
    k_gemm1<<<(NN + 127) / 128, 256>>>(x, W1, att_src1, att_dst1);

    // join: aggregation needs both CSR and GEMM1
    cudaStreamWaitEvent(0, e_join, 0);

    // layer-1 aggregation fused with layer-2 linear + att coeffs
    k_agg1<<<(NN + 7) / 8, 256>>>(b1, W2, att_src2, att_dst2);

    // layer-2 aggregation + log_softmax
    k_agg2<<<(NN + 7) / 8, 256>>>(b2, out);
}

// round 10
// speedup vs baseline: 1.4372x; 1.0462x over previous
#include <cuda_runtime.h>
#include <cuda_fp16.h>
#include <cstdint>

#define NN   50000
#define EE   1600000
#define FIN  512
#define F1   64        // H1*C1
#define NH1  8
#define C2   40
#define NBLK 196       // ceil(NN/256)
#define FULLM 0xffffffffu
#define LOG2E 1.4426950408889634f

// ------------------------- scratch (static device memory; no allocs allowed)
__device__ __half g_h1h[NN * F1];      // layer1 features, fp16 (gather payload)
__device__ __half g_as1h[NN * NH1];    // alpha_src1 * log2e, fp16
__device__ __half g_ad1h[NN * NH1];    // alpha_dst1 * log2e, fp16
__device__ __half g_h2h[NN * C2];      // layer2 linear out, fp16 (gather payload)
__device__ float  g_as2[NN];
__device__ float  g_ad2[NN];
__device__ int    g_deg[NN];
__device__ int    g_rowloc[NN];
__device__ int    g_bsum[256];
__device__ int    g_boff[256];
__device__ int    g_rowptr[NN + 1];
__device__ int    g_cursor[NN];
__device__ int    g_col[EE];

__device__ __forceinline__ float leaky(float v) { return v > 0.f ? v : 0.2f * v; }

__device__ __forceinline__ uint32_t f2tf(float f) {
    uint32_t u;
    asm("cvt.rna.tf32.f32 %0, %1;" : "=r"(u) : "f"(f));
    return u;
}

__device__ __forceinline__ void mma_tf32(float* d, const uint32_t* a, const uint32_t* b) {
    asm volatile(
        "mma.sync.aligned.m16n8k8.row.col.f32.tf32.tf32.f32 "
        "{%0,%1,%2,%3}, {%4,%5,%6,%7}, {%8,%9}, {%0,%1,%2,%3};"
        : "+f"(d[0]), "+f"(d[1]), "+f"(d[2]), "+f"(d[3])
        : "r"(a[0]), "r"(a[1]), "r"(a[2]), "r"(a[3]), "r"(b[0]), "r"(b[1]));
}

__device__ __forceinline__ __half2 h2ex2(__half2 x) {
    __half2 r;
    asm("ex2.approx.f16x2 %0, %1;"
        : "=r"(*(uint32_t*)&r) : "r"(*(uint32_t*)&x));
    return r;
}
__device__ __forceinline__ __half2 u2h2(uint32_t u) { return *(__half2*)&u; }

// ------------------------- GEMM1 (tf32 tensor cores) + fused attention coeffs
__global__ __launch_bounds__(256) void k_gemm1(const float* __restrict__ x,
                                               const float* __restrict__ W1,
                                               const float* __restrict__ attS,
                                               const float* __restrict__ attD) {
    __shared__ float sA[128][36];
    __shared__ float sB[32][72];
    __shared__ float sAs[64], sAd[64];

    const int t    = threadIdx.x;
    const int wid  = t >> 5;
    const int lane = t & 31;
    const int m0   = blockIdx.x * 128;
    const int warp_m = (wid >> 1) * 32;
    const int warp_n = (wid & 1) * 32;
    if (t < 64) { sAs[t] = attS[t]; sAd[t] = attD[t]; }

    float acc[2][4][4];
#pragma unroll
    for (int mi = 0; mi < 2; mi++)
#pragma unroll
        for (int ni = 0; ni < 4; ni++)
#pragma unroll
            for (int e = 0; e < 4; e++) acc[mi][ni][e] = 0.f;

    const int r = lane >> 2;
    const int c = lane & 3;
    const int arow = t >> 3;
    const int acol = (t & 7) * 4;

    for (int kc = 0; kc < FIN; kc += 32) {
#pragma unroll
        for (int i = 0; i < 4; i++) {
            int row = i * 32 + arow;
            int gm  = m0 + row;
            float4 v = (gm < NN) ? *(const float4*)&x[(long)gm * FIN + kc + acol]
                                 : make_float4(0.f, 0.f, 0.f, 0.f);
            float4 tv;
            tv.x = __uint_as_float(f2tf(v.x));
            tv.y = __uint_as_float(f2tf(v.y));
            tv.z = __uint_as_float(f2tf(v.z));
            tv.w = __uint_as_float(f2tf(v.w));
            *(float4*)&sA[row][acol] = tv;
        }
#pragma unroll
        for (int i = 0; i < 2; i++) {
            int f   = t + i * 256;
            int row = f >> 4;
            int c4  = (f & 15) * 4;
            float4 v = *(const float4*)&W1[(kc + row) * F1 + c4];
            float4 tv;
            tv.x = __uint_as_float(f2tf(v.x));
            tv.y = __uint_as_float(f2tf(v.y));
            tv.z = __uint_as_float(f2tf(v.z));
            tv.w = __uint_as_float(f2tf(v.w));
            *(float4*)&sB[row][c4] = tv;
        }
        __syncthreads();

#pragma unroll
        for (int ks = 0; ks < 4; ks++) {
            const int k0 = ks * 8;
            uint32_t afrag[2][4];
#pragma unroll
            for (int mi = 0; mi < 2; mi++) {
                int mm = warp_m + mi * 16;
                afrag[mi][0] = __float_as_uint(sA[mm + r][k0 + c]);
                afrag[mi][1] = __float_as_uint(sA[mm + r + 8][k0 + c]);
                afrag[mi][2] = __float_as_uint(sA[mm + r][k0 + c + 4]);
                afrag[mi][3] = __float_as_uint(sA[mm + r + 8][k0 + c + 4]);
            }
            uint32_t bfrag[4][2];
#pragma unroll
            for (int ni = 0; ni < 4; ni++) {
                int nn = warp_n + ni * 8;
                bfrag[ni][0] = __float_as_uint(sB[k0 + c][nn + r]);
                bfrag[ni][1] = __float_as_uint(sB[k0 + c + 4][nn + r]);
            }
#pragma unroll
            for (int mi = 0; mi < 2; mi++)
#pragma unroll
                for (int ni = 0; ni < 4; ni++)
                    mma_tf32(acc[mi][ni], afrag[mi], bfrag[ni]);
        }
        __syncthreads();
    }

#pragma unroll
    for (int mi = 0; mi < 2; mi++) {
        int row_g = m0 + warp_m + mi * 16 + r;
        int row_h = row_g + 8;
#pragma unroll
        for (int ni = 0; ni < 4; ni++) {
            int nn = warp_n + ni * 8;
            int col = nn + c * 2;
            if (row_g < NN)
                *(__half2*)&g_h1h[row_g * F1 + col] = __floats2half2_rn(acc[mi][ni][0], acc[mi][ni][1]);
            if (row_h < NN)
                *(__half2*)&g_h1h[row_h * F1 + col] = __floats2half2_rn(acc[mi][ni][2], acc[mi][ni][3]);
            float as0 = sAs[col], as1v = sAs[col + 1];
            float ad0 = sAd[col], ad1v = sAd[col + 1];
            float psg = acc[mi][ni][0] * as0 + acc[mi][ni][1] * as1v;
            float pdg = acc[mi][ni][0] * ad0 + acc[mi][ni][1] * ad1v;
            float psh = acc[mi][ni][2] * as0 + acc[mi][ni][3] * as1v;
            float pdh = acc[mi][ni][2] * ad0 + acc[mi][ni][3] * ad1v;
#pragma unroll
            for (int off = 1; off <= 2; off <<= 1) {
                psg += __shfl_xor_sync(FULLM, psg, off);
                pdg += __shfl_xor_sync(FULLM, pdg, off);
                psh += __shfl_xor_sync(FULLM, psh, off);
                pdh += __shfl_xor_sync(FULLM, pdh, off);
            }
            int h = nn >> 3;
            if (c == 0) {
                if (row_g < NN) {
                    g_as1h[row_g * NH1 + h] = __float2half_rn(psg * LOG2E);
                    g_ad1h[row_g * NH1 + h] = __float2half_rn(pdg * LOG2E);
                }
                if (row_h < NN) {
                    g_as1h[row_h * NH1 + h] = __float2half_rn(psh * LOG2E);
                    g_ad1h[row_h * NH1 + h] = __float2half_rn(pdh * LOG2E);
                }
            }
        }
    }
}

// ------------------------- CSR build
__global__ void k_zero() {
    int i = blockIdx.x * blockDim.x + threadIdx.x;
    if (i < NN) g_deg[i] = 0;
}
__global__ void k_hist(const int* __restrict__ dst) {
    int e = blockIdx.x * blockDim.x + threadIdx.x;
    if (e < EE) atomicAdd(&g_deg[dst[e]], 1);
}
__global__ __launch_bounds__(256) void k_part() {
    __shared__ int sm[256];
    int t = threadIdx.x, i = blockIdx.x * 256 + t;
    int d = (i < NN) ? g_deg[i] : 0;
    sm[t] = d;
    __syncthreads();
#pragma unroll
    for (int off = 1; off < 256; off <<= 1) {
        int v = (t >= off) ? sm[t - off] : 0;
        __syncthreads();
        sm[t] += v;
        __syncthreads();
    }
    if (i < NN) g_rowloc[i] = sm[t] - d;
    if (t == 255) g_bsum[blockIdx.x] = sm[255];
}
__global__ __launch_bounds__(256) void k_bscan() {
    __shared__ int sm[256];
    int t = threadIdx.x;
    int d = (t < NBLK) ? g_bsum[t] : 0;
    sm[t] = d;
    __syncthreads();
#pragma unroll
    for (int off = 1; off < 256; off <<= 1) {
        int v = (t >= off) ? sm[t - off] : 0;
        __syncthreads();
        sm[t] += v;
        __syncthreads();
    }
    if (t < NBLK) g_boff[t] = sm[t] - d;
    if (t == NBLK - 1) g_rowptr[NN] = sm[t];
}
__global__ void k_fix() {
    int i = blockIdx.x * blockDim.x + threadIdx.x;
    if (i < NN) {
        int rp = g_rowloc[i] + g_boff[blockIdx.x];
        g_rowptr[i] = rp;
        g_cursor[i] = rp;
    }
}
__global__ void k_scatter(const int* __restrict__ src, const int* __restrict__ dst) {
    int e = blockIdx.x * blockDim.x + threadIdx.x;
    if (e < EE) {
        int d = dst[e];
        int p = atomicAdd(&g_cursor[d], 1);
        g_col[p] = src[e];
    }
}

// ------------------------- layer-1 aggregation + fused layer-2 linear/att
// one warp per dst node; 8-wide batched gathers (explicit MLP)
__global__ __launch_bounds__(256) void k_agg1(const float* __restrict__ b1,
                                              const float* __restrict__ W2,
                                              const float* __restrict__ att_s,
                                              const float* __restrict__ att_d) {
    __shared__ float swt[8][8][36];
    __shared__ int   ssrc[8][32];
    __shared__ float sW2[F1 * C2];
    __shared__ float sAs2[C2], sAd2[C2];

    for (int idx = threadIdx.x; idx < F1 * C2; idx += 256) sW2[idx] = W2[idx];
    if (threadIdx.x < C2) {
        sAs2[threadIdx.x] = att_s[threadIdx.x];
        sAd2[threadIdx.x] = att_d[threadIdx.x];
    }
    __syncthreads();

    const int w    = threadIdx.x >> 5;
    const int lane = threadIdx.x & 31;
    const int node = blockIdx.x * 8 + w;
    if (node >= NN) return;
    const int beg   = g_rowptr[node];
    const int deg   = g_rowptr[node + 1] - beg;
    const int total = deg + 1;

    const __half2 k02 = __floats2half2_rn(0.2f, 0.2f);
    int4 adv = *(const int4*)&g_ad1h[node * NH1];
    __half2 adp[4] = { u2h2(adv.x), u2h2(adv.y), u2h2(adv.z), u2h2(adv.w) };

    const int hl = lane >> 2;
    const int c0 = lane * 2;
    float acc0 = 0.f, acc1 = 0.f;
    float ssum[8];
#pragma unroll
    for (int h = 0; h < 8; h++) ssum[h] = 0.f;

    for (int k0 = 0; k0 < total; k0 += 32) {
        int kk  = k0 + lane;
        int lim = min(32, total - k0);
        __syncwarp();
        if (kk < total) {
            int srcn = (kk < deg) ? g_col[beg + kk] : node;
            int4 sv = *(const int4*)&g_as1h[srcn * NH1];
            __half2 sp[4] = { u2h2(sv.x), u2h2(sv.y), u2h2(sv.z), u2h2(sv.w) };
#pragma unroll
            for (int p = 0; p < 4; p++) {
                __half2 l = __hadd2(sp[p], adp[p]);                  // (as+ad)*log2e
                __half2 lk = __hmax2(l, __hmul2(l, k02));            // leaky (exact)
                float2 f = __half22float2(h2ex2(lk));                // exp via ex2
                ssum[2 * p]     += f.x;
                ssum[2 * p + 1] += f.y;
                swt[w][2 * p][lane]     = f.x;
                swt[w][2 * p + 1][lane] = f.y;
            }
            ssrc[w][lane] = srcn;
        }
        __syncwarp();
        // 8-wide batched gather: force 8 independent LDGs in flight
        int j = 0;
        for (; j + 8 <= lim; j += 8) {
            int   sn[8];
            float wt[8];
            float2 pv[8];
#pragma unroll
            for (int q = 0; q < 8; q++) {
                sn[q] = ssrc[w][j + q];
                wt[q] = swt[w][hl][j + q];
            }
#pragma unroll
            for (int q = 0; q < 8; q++)
                pv[q] = __half22float2(*(const __half2*)&g_h1h[sn[q] * F1 + c0]);
#pragma unroll
            for (int q = 0; q < 8; q++) {
                acc0 += wt[q] * pv[q].x;
                acc1 += wt[q] * pv[q].y;
            }
        }
        for (; j < lim; j++) {
            int srcn = ssrc[w][j];
            float wt = swt[w][hl][j];
            float2 hv = __half22float2(*(const __half2*)&g_h1h[srcn * F1 + c0]);
            acc0 += wt * hv.x;
            acc1 += wt * hv.y;
        }
    }
#pragma unroll
    for (int h = 0; h < 8; h++) {
#pragma unroll
        for (int off = 16; off > 0; off >>= 1)
            ssum[h] += __shfl_xor_sync(FULLM, ssum[h], off);
    }
    float myS = 0.f;
#pragma unroll
    for (int h = 0; h < 8; h++)
        if (hl == h) myS = ssum[h];
    float inv = __fdividef(1.0f, myS);

    // x2 row in registers (relu + bias)
    float v0 = fmaxf(acc0 * inv + b1[c0], 0.f);
    float v1 = fmaxf(acc1 * inv + b1[c0 + 1], 0.f);

    // fused layer-2 linear: h2 = x2 @ W2  (+ attention coefficients)
    const int cA = lane;
    const int cB = lane + 32;
    const bool has1 = (lane < 8);
    float a0 = 0.f, a1 = 0.f;
#pragma unroll
    for (int kk = 0; kk < 32; kk++) {
        float x0 = __shfl_sync(FULLM, v0, kk);
        float x1 = __shfl_sync(FULLM, v1, kk);
        a0 += x0 * sW2[(2 * kk) * C2 + cA] + x1 * sW2[(2 * kk + 1) * C2 + cA];
        if (has1)
            a1 += x0 * sW2[(2 * kk) * C2 + cB] + x1 * sW2[(2 * kk + 1) * C2 + cB];
    }
    g_h2h[node * C2 + cA] = __float2half_rn(a0);
    if (has1) g_h2h[node * C2 + cB] = __float2half_rn(a1);

    float ps = a0 * sAs2[cA] + (has1 ? a1 * sAs2[cB] : 0.f);
    float pd = a0 * sAd2[cA] + (has1 ? a1 * sAd2[cB] : 0.f);
#pragma unroll
    for (int off = 16; off > 0; off >>= 1) {
        ps += __shfl_xor_sync(FULLM, ps, off);
        pd += __shfl_xor_sync(FULLM, pd, off);
    }
    if (lane == 0) { g_as2[node] = ps; g_ad2[node] = pd; }
}

// ------------------------- layer-2 aggregation + bias + log_softmax
// one warp per node; 20 lanes own channel PAIRS; 8-wide batched gathers
__global__ __launch_bounds__(256) void k_agg2(const float* __restrict__ b2,
                                              float* __restrict__ out) {
    __shared__ float swt[8][32];
    __shared__ int   ssrc[8][32];
    const int w    = threadIdx.x >> 5;
    const int lane = threadIdx.x & 31;
    const int node = blockIdx.x * 8 + w;
    if (node >= NN) return;
    const int beg   = g_rowptr[node];
    const int deg   = g_rowptr[node + 1] - beg;
    const int total = deg + 1;
    const float adn = g_ad2[node];

    const bool active = (lane < 20);        // channel pair 2*lane, 2*lane+1
    const int cp = lane * 2;
    float acc0 = 0.f, acc1 = 0.f, ssum = 0.f;
    for (int k0 = 0; k0 < total; k0 += 32) {
        int kk  = k0 + lane;
        int lim = min(32, total - k0);
        __syncwarp();
        if (kk < total) {
            int srcn = (kk < deg) ? g_col[beg + kk] : node;
            float wt = __expf(leaky(g_as2[srcn] + adn));
            ssum += wt;
            swt[w][lane]  = wt;
            ssrc[w][lane] = srcn;
        }
        __syncwarp();
        if (active) {
            int j = 0;
            for (; j + 8 <= lim; j += 8) {
                int   sn[8];
                float wt[8];
                float2 pv[8];
#pragma unroll
                for (int q = 0; q < 8; q++) {
                    sn[q] = ssrc[w][j + q];
                    wt[q] = swt[w][j + q];
                }
#pragma unroll
                for (int q = 0; q < 8; q++)
                    pv[q] = __half22float2(*(const __half2*)&g_h2h[sn[q] * C2 + cp]);
#pragma unroll
                for (int q = 0; q < 8; q++) {
                    acc0 += wt[q] * pv[q].x;
                    acc1 += wt[q] * pv[q].y;
                }
            }
            for (; j < lim; j++) {
                int srcn = ssrc[w][j];
                float wt = swt[w][j];
                float2 hv = __half22float2(*(const __half2*)&g_h2h[srcn * C2 + cp]);
                acc0 += wt * hv.x;
                acc1 += wt * hv.y;
            }
        }
    }
#pragma unroll
    for (int off = 16; off > 0; off >>= 1)
        ssum += __shfl_xor_sync(FULLM, ssum, off);
    float inv = __fdividef(1.0f, ssum);

    float o0 = active ? (acc0 * inv + b2[cp])     : -1e30f;
    float o1 = active ? (acc1 * inv + b2[cp + 1]) : -1e30f;

    float mx = fmaxf(o0, o1);
#pragma unroll
    for (int off = 16; off > 0; off >>= 1)
        mx = fmaxf(mx, __shfl_xor_sync(FULLM, mx, off));
    float se = active ? (__expf(o0 - mx) + __expf(o1 - mx)) : 0.f;
#pragma unroll
    for (int off = 16; off > 0; off >>= 1)
        se += __shfl_xor_sync(FULLM, se, off);
    float lse = mx + __logf(se);

    if (active)
        *(float2*)&out[node * C2 + cp] = make_float2(o0 - lse, o1 - lse);
}

// ------------------------- launch (CSR build overlapped with GEMM1)
extern "C" void kernel_launch(void* const* d_in, const int* in_sizes, int n_in,
                              void* d_out, int out_size) {
    const float* x        = (const float*)d_in[0];
    const int*   ei       = (const int*)d_in[1];
    const float* W1       = (const float*)d_in[2];
    const float* att_src1 = (const float*)d_in[3];
    const float* att_dst1 = (const float*)d_in[4];
    const float* b1       = (const float*)d_in[5];
    const float* W2       = (const float*)d_in[6];
    const float* att_src2 = (const float*)d_in[7];
    const float* att_dst2 = (const float*)d_in[8];
    const float* b2       = (const float*)d_in[9];
    float* out = (float*)d_out;

    const int* src = ei;
    const int* dst = ei + EE;

    // one-time host-side resources (identical GPU work every call)
    static cudaStream_t s_csr = nullptr;
    static cudaEvent_t  e_fork = nullptr, e_join = nullptr;
    if (s_csr == nullptr) {
        cudaStreamCreateWithFlags(&s_csr, cudaStreamNonBlocking);
        cudaEventCreateWithFlags(&e_fork, cudaEventDisableTiming);
        cudaEventCreateWithFlags(&e_join, cudaEventDisableTiming);
    }

    // fork: CSR build on side stream
    cudaEventRecord(e_fork, 0);
    cudaStreamWaitEvent(s_csr, e_fork, 0);
    k_zero<<<(NN + 255) / 256, 256, 0, s_csr>>>();
    k_hist<<<(EE + 255) / 256, 256, 0, s_csr>>>(dst);
    k_part<<<NBLK, 256, 0, s_csr>>>();
    k_bscan<<<1, 256, 0, s_csr>>>();
    k_fix<<<NBLK, 256, 0, s_csr>>>();
    k_scatter<<<(EE + 255) / 256, 256, 0, s_csr>>>(src, dst);
    cudaEventRecord(e_join, s_csr);

    // concurrent: layer-1 GEMM (tf32 tensor cores + fused att coeffs)
    k_gemm1<<<(NN + 127) / 128, 256>>>(x, W1, att_src1, att_dst1);

    // join: aggregation needs both CSR and GEMM1
    cudaStreamWaitEvent(0, e_join, 0);

    // layer-1 aggregation fused with layer-2 linear + att coeffs
    k_agg1<<<(NN + 7) / 8, 256>>>(b1, W2, att_src2, att_dst2);

    // layer-2 aggregation + log_softmax
    k_agg2<<<(NN + 7) / 8, 256>>>(b2, out);
}